// round 8
// baseline (speedup 1.0000x reference)
#include <cuda_runtime.h>
#include <cuda_bf16.h>

#define N_NODES  100000
#define N_EDGES  1600000
#define HID      128
#define KPW      64
#define N_GRAPHS 64
#define N_CLASSES 10
#define PADROWS  128
#define SCAN_BLOCKS 98

// ---------------- scratch ----------------
__device__ float    g_A32[(N_NODES + PADROWS) * HID];   // final layer-3 output (pool input)
__device__ unsigned g_Ahh[(N_NODES + PADROWS) * KPW];
__device__ unsigned g_Ahl[(N_NODES + PADROWS) * KPW];
__device__ unsigned g_Bhh[(N_NODES + PADROWS) * KPW];
__device__ unsigned g_Bhl[(N_NODES + PADROWS) * KPW];
__device__ unsigned g_Mh[(N_NODES + PADROWS) * KPW];
__device__ unsigned g_Ml[(N_NODES + PADROWS) * KPW];
__device__ float g_meanx[N_NODES];
__device__ int   g_cnt[N_NODES];
__device__ int   g_off[N_NODES + 1];
__device__ int   g_cur[N_NODES];
__device__ int   g_eidx[N_EDGES];
__device__ float g_pool[N_GRAPHS * HID];
__device__ int   g_pcnt[N_GRAPHS];
__device__ int   g_bsum[128];
__device__ int   g_bpre[128];
__device__ unsigned g_Wph[2 * 128 * 128];
__device__ unsigned g_Wpl[2 * 128 * 128];

// ---------------- helpers ----------------
__device__ __forceinline__ void split2(float v0, float v1, unsigned& wh, unsigned& wl) {
    __nv_bfloat162 h = __floats2bfloat162_rn(v0, v1);
    wh = *(unsigned*)&h;
    float h0f = __uint_as_float(wh << 16);
    float h1f = __uint_as_float(wh & 0xFFFF0000u);
    __nv_bfloat162 l = __floats2bfloat162_rn(v0 - h0f, v1 - h1f);
    wl = *(unsigned*)&l;
}

__device__ __forceinline__ void mma16816(float* c, const unsigned* a, const unsigned* b) {
    asm volatile(
        "mma.sync.aligned.m16n8k16.row.col.f32.bf16.bf16.f32 "
        "{%0,%1,%2,%3},{%4,%5,%6,%7},{%8,%9},{%0,%1,%2,%3};\n"
        : "+f"(c[0]), "+f"(c[1]), "+f"(c[2]), "+f"(c[3])
        : "r"(a[0]), "r"(a[1]), "r"(a[2]), "r"(a[3]), "r"(b[0]), "r"(b[1]));
}

// ---------------- zero ----------------
__global__ void k_zero() {
    int i = blockIdx.x * blockDim.x + threadIdx.x;
    if (i < N_NODES) g_cnt[i] = 0;
    if (i < N_GRAPHS * HID) g_pool[i] = 0.f;
    if (i < N_GRAPHS) g_pcnt[i] = 0;
}

__global__ void k_hist(const int* __restrict__ dst) {
    int e = blockIdx.x * blockDim.x + threadIdx.x;
    if (e < N_EDGES) atomicAdd(&g_cnt[dst[e]], 1);
}

// ---------------- multi-block scan ----------------
__global__ void k_scan1() {
    __shared__ int warpsum[32];
    const int t = threadIdx.x, lane = t & 31, wid = t >> 5;
    int i = blockIdx.x * 1024 + t;
    int v = (i < N_NODES) ? g_cnt[i] : 0;
    int x = v;
    #pragma unroll
    for (int o = 1; o < 32; o <<= 1) {
        int y = __shfl_up_sync(0xffffffff, x, o);
        if (lane >= o) x += y;
    }
    if (lane == 31) warpsum[wid] = x;
    __syncthreads();
    if (wid == 0) {
        int w = warpsum[lane];
        int xs = w;
        #pragma unroll
        for (int o = 1; o < 32; o <<= 1) {
            int y = __shfl_up_sync(0xffffffff, xs, o);
            if (lane >= o) xs += y;
        }
        warpsum[lane] = xs - w;
    }
    __syncthreads();
    int excl = warpsum[wid] + x - v;
    if (i < N_NODES) g_off[i] = excl;
    if (t == 1023) g_bsum[blockIdx.x] = excl + v;
}

__global__ void k_scan2() {
    __shared__ int wsum[4];
    const int t = threadIdx.x, lane = t & 31, wid = t >> 5;
    int v = (t < SCAN_BLOCKS) ? g_bsum[t] : 0;
    int x = v;
    #pragma unroll
    for (int o = 1; o < 32; o <<= 1) {
        int y = __shfl_up_sync(0xffffffff, x, o);
        if (lane >= o) x += y;
    }
    if (lane == 31) wsum[wid] = x;
    __syncthreads();
    int pre = 0;
    #pragma unroll
    for (int wdx = 0; wdx < 4; wdx++) if (wdx < wid) pre += wsum[wdx];
    int excl = pre + x - v;
    if (t < SCAN_BLOCKS) g_bpre[t] = excl;
    if (t == SCAN_BLOCKS - 1) g_off[N_NODES] = excl + v;
}

__global__ void k_scan3() {
    int i = blockIdx.x * 1024 + threadIdx.x;
    if (i < N_NODES) {
        int o = g_off[i] + g_bpre[blockIdx.x];
        g_off[i] = o;
        g_cur[i] = o;
    }
}

__global__ void k_scatter(const int* __restrict__ src, const int* __restrict__ dst) {
    int e = blockIdx.x * blockDim.x + threadIdx.x;
    if (e < N_EDGES) {
        int pos = atomicAdd(&g_cur[dst[e]], 1);
        g_eidx[pos] = src[e];
    }
}

// ---------------- weight convert ----------------
__global__ void k_convW(const float* __restrict__ W2l, const float* __restrict__ W2r,
                        const float* __restrict__ W3l, const float* __restrict__ W3r) {
    int idx = blockIdx.x * blockDim.x + threadIdx.x;
    if (idx >= 2 * 128 * 128) return;
    int layer = idx >> 14;
    int rem = idx & 16383;
    int n = rem >> 7;
    int kp = rem & 127;
    const float* W = (kp < 64) ? (layer ? W3l : W2l) : (layer ? W3r : W2r);
    int k = (kp < 64) ? (2 * kp) : (2 * kp - 128);
    float v0 = W[k * HID + n];
    float v1 = W[(k + 1) * HID + n];
    unsigned wh, wl;
    split2(v0, v1, wh, wl);
    g_Wph[idx] = wh;
    g_Wpl[idx] = wl;
}

// ---------------- layer-1 scalar aggregation ----------------
__global__ void k_aggx(const float* __restrict__ x) {
    int i = blockIdx.x * blockDim.x + threadIdx.x;
    if (i >= N_NODES) return;
    int b = g_off[i], e = g_off[i + 1];
    float s0 = 0.f, s1 = 0.f, s2 = 0.f, s3 = 0.f;
    int j = b;
    for (; j + 4 <= e; j += 4) {
        s0 += __ldg(&x[g_eidx[j]]);
        s1 += __ldg(&x[g_eidx[j + 1]]);
        s2 += __ldg(&x[g_eidx[j + 2]]);
        s3 += __ldg(&x[g_eidx[j + 3]]);
    }
    for (; j < e; j++) s0 += __ldg(&x[g_eidx[j]]);
    g_meanx[i] = (s0 + s1 + s2 + s3) / (float)max(e - b, 1);
}

// ---------------- layer 1: split-format output only ----------------
__global__ void k_layer1(const float* __restrict__ x,
                         const float* __restrict__ W1l,
                         const float* __restrict__ W1r,
                         const float* __restrict__ b1,
                         unsigned* __restrict__ Oh, unsigned* __restrict__ Ol) {
    int idx = blockIdx.x * blockDim.x + threadIdx.x;
    if (idx >= N_NODES * KPW) return;
    int i = idx >> 6, wq = idx & 63;
    int f0 = wq * 2;
    float mx = g_meanx[i], xi = __ldg(&x[i]);
    float v0 = fmaxf(mx * __ldg(&W1l[f0]) + xi * __ldg(&W1r[f0]) + __ldg(&b1[f0]), 0.f);
    float v1 = fmaxf(mx * __ldg(&W1l[f0 + 1]) + xi * __ldg(&W1r[f0 + 1]) + __ldg(&b1[f0 + 1]), 0.f);
    unsigned wh, wl;
    split2(v0, v1, wh, wl);
    Oh[idx] = wh;
    Ol[idx] = wl;
}

// ---------------- mean aggregation: bf16-hi gather (half traffic) -------------
__global__ void k_agg(const unsigned* __restrict__ Hh,
                      unsigned* __restrict__ Mh, unsigned* __restrict__ Ml) {
    int node = (blockIdx.x * blockDim.x + threadIdx.x) >> 5;
    int lane = threadIdx.x & 31;
    if (node >= N_NODES) return;
    int beg = g_off[node], end = g_off[node + 1];
    const uint2* hv = (const uint2*)Hh;      // 2 words = 4 features per lane
    float a0 = 0.f, a1 = 0.f, a2 = 0.f, a3 = 0.f;
    float b0 = 0.f, b1 = 0.f, b2 = 0.f, b3 = 0.f;
    int e = beg;
    for (; e + 4 <= end; e += 4) {
        int s0 = __ldg(&g_eidx[e]);
        int s1 = __ldg(&g_eidx[e + 1]);
        int s2 = __ldg(&g_eidx[e + 2]);
        int s3 = __ldg(&g_eidx[e + 3]);
        uint2 v0 = __ldg(&hv[s0 * 32 + lane]);
        uint2 v1 = __ldg(&hv[s1 * 32 + lane]);
        uint2 v2 = __ldg(&hv[s2 * 32 + lane]);
        uint2 v3 = __ldg(&hv[s3 * 32 + lane]);
        a0 += __uint_as_float(v0.x << 16);  a1 += __uint_as_float(v0.x & 0xFFFF0000u);
        a2 += __uint_as_float(v0.y << 16);  a3 += __uint_as_float(v0.y & 0xFFFF0000u);
        b0 += __uint_as_float(v1.x << 16);  b1 += __uint_as_float(v1.x & 0xFFFF0000u);
        b2 += __uint_as_float(v1.y << 16);  b3 += __uint_as_float(v1.y & 0xFFFF0000u);
        a0 += __uint_as_float(v2.x << 16);  a1 += __uint_as_float(v2.x & 0xFFFF0000u);
        a2 += __uint_as_float(v2.y << 16);  a3 += __uint_as_float(v2.y & 0xFFFF0000u);
        b0 += __uint_as_float(v3.x << 16);  b1 += __uint_as_float(v3.x & 0xFFFF0000u);
        b2 += __uint_as_float(v3.y << 16);  b3 += __uint_as_float(v3.y & 0xFFFF0000u);
    }
    for (; e < end; e++) {
        int s = __ldg(&g_eidx[e]);
        uint2 v = __ldg(&hv[s * 32 + lane]);
        a0 += __uint_as_float(v.x << 16);  a1 += __uint_as_float(v.x & 0xFFFF0000u);
        a2 += __uint_as_float(v.y << 16);  a3 += __uint_as_float(v.y & 0xFFFF0000u);
    }
    float inv = 1.f / (float)max(end - beg, 1);
    unsigned wh0, wl0, wh1, wl1;
    split2((a0 + b0) * inv, (a1 + b1) * inv, wh0, wl0);
    split2((a2 + b2) * inv, (a3 + b3) * inv, wh1, wl1);
    *(uint2*)&Mh[node * KPW + lane * 2] = make_uint2(wh0, wh1);
    *(uint2*)&Ml[node * KPW + lane * 2] = make_uint2(wl0, wl1);
}

// ---------------- tensor-core GEMM, conversion-free, 2-stage cp.async ---------
#define TSTR 20
#define PART_W 2560
#define STAGE_W (4 * PART_W)
__global__ __launch_bounds__(256, 2) void k_gemm_tc(
    const unsigned* __restrict__ Mh_, const unsigned* __restrict__ Ml_,
    const unsigned* __restrict__ Hh_, const unsigned* __restrict__ Hl_,
    const unsigned* __restrict__ Wph, const unsigned* __restrict__ Wpl,
    const float* __restrict__ bias,
    float* __restrict__ O32,
    unsigned* __restrict__ Oh, unsigned* __restrict__ Ol,
    int storeF32, int storeSplit)
{
    extern __shared__ unsigned sm[];
    const int t = threadIdx.x, lane = t & 31, w = t >> 5;
    const int wm = w >> 2, wn = w & 3;
    const int g = lane >> 2, tid4 = lane & 3;
    const int m0 = blockIdx.x * 128;

    auto fill = [&](int stage, int kb) {
        const unsigned* Ah_ = (kb < 4) ? Mh_ : Hh_;
        const unsigned* Al_ = (kb < 4) ? Ml_ : Hl_;
        const int koff = (kb & 3) * 16;
        const unsigned base = stage * STAGE_W;
        #pragma unroll
        for (int i = 0; i < 8; i++) {
            int id = t + 256 * i;
            int part = id >> 9;
            int rem = id & 511;
            int r = rem >> 2, wq = (rem & 3) * 4;
            const unsigned* src;
            if (part == 0)      src = Ah_ + (m0 + r) * KPW + koff + wq;
            else if (part == 1) src = Al_ + (m0 + r) * KPW + koff + wq;
            else if (part == 2) src = Wph + r * 128 + kb * 16 + wq;
            else                src = Wpl + r * 128 + kb * 16 + wq;
            unsigned daddr = (unsigned)__cvta_generic_to_shared(sm + base + part * PART_W + r * TSTR + wq);
            asm volatile("cp.async.cg.shared.global [%0],[%1],16;\n" :: "r"(daddr), "l"(src));
        }
        asm volatile("cp.async.commit_group;\n");
    };

    float acc[4][4][4];
    #pragma unroll
    for (int a = 0; a < 4; a++)
        #pragma unroll
        for (int b = 0; b < 4; b++)
            #pragma unroll
            for (int c = 0; c < 4; c++) acc[a][b][c] = 0.f;

    fill(0, 0);
    fill(1, 1);

    for (int kb = 0; kb < 8; kb++) {
        if (kb < 7) asm volatile("cp.async.wait_group 1;\n");
        else        asm volatile("cp.async.wait_group 0;\n");
        __syncthreads();
        const unsigned base = (kb & 1) * STAGE_W;
        const unsigned* Ash = sm + base;
        const unsigned* Asl = sm + base + PART_W;
        const unsigned* Wsh = sm + base + 2 * PART_W;
        const unsigned* Wsl = sm + base + 3 * PART_W;
        #pragma unroll
        for (int ks = 0; ks < 2; ks++) {
            const int kp0 = ks * 8 + tid4;
            unsigned ah[4][4], al[4][4], bh[4][2], bl[4][2];
            #pragma unroll
            for (int mt = 0; mt < 4; mt++) {
                int r = wm * 64 + mt * 16 + g;
                ah[mt][0] = Ash[r * TSTR + kp0];       ah[mt][1] = Ash[(r + 8) * TSTR + kp0];
                ah[mt][2] = Ash[r * TSTR + kp0 + 4];   ah[mt][3] = Ash[(r + 8) * TSTR + kp0 + 4];
                al[mt][0] = Asl[r * TSTR + kp0];       al[mt][1] = Asl[(r + 8) * TSTR + kp0];
                al[mt][2] = Asl[r * TSTR + kp0 + 4];   al[mt][3] = Asl[(r + 8) * TSTR + kp0 + 4];
            }
            #pragma unroll
            for (int nt = 0; nt < 4; nt++) {
                int n = wn * 32 + nt * 8 + g;
                bh[nt][0] = Wsh[n * TSTR + kp0]; bh[nt][1] = Wsh[n * TSTR + kp0 + 4];
                bl[nt][0] = Wsl[n * TSTR + kp0]; bl[nt][1] = Wsl[n * TSTR + kp0 + 4];
            }
            #pragma unroll
            for (int mt = 0; mt < 4; mt++)
                #pragma unroll
                for (int nt = 0; nt < 4; nt++) {
                    mma16816(acc[mt][nt], ah[mt], bh[nt]);
                    mma16816(acc[mt][nt], ah[mt], bl[nt]);
                    mma16816(acc[mt][nt], al[mt], bh[nt]);
                }
        }
        __syncthreads();
        if (kb + 2 < 8) fill(kb & 1, kb + 2);
    }

    #pragma unroll
    for (int nt = 0; nt < 4; nt++) {
        int colw = wn * 16 + nt * 4 + tid4;
        int col = colw * 2;
        float b0 = __ldg(&bias[col]), b1 = __ldg(&bias[col + 1]);
        #pragma unroll
        for (int mt = 0; mt < 4; mt++) {
            int row = m0 + wm * 64 + mt * 16 + g;
            float v0 = fmaxf(acc[mt][nt][0] + b0, 0.f);
            float v1 = fmaxf(acc[mt][nt][1] + b1, 0.f);
            float v2 = fmaxf(acc[mt][nt][2] + b0, 0.f);
            float v3 = fmaxf(acc[mt][nt][3] + b1, 0.f);
            if (storeF32) {
                *(float2*)&O32[row * HID + col] = make_float2(v0, v1);
                *(float2*)&O32[(row + 8) * HID + col] = make_float2(v2, v3);
            }
            if (storeSplit) {
                unsigned wh, wl;
                split2(v0, v1, wh, wl);
                Oh[row * KPW + colw] = wh;
                Ol[row * KPW + colw] = wl;
                split2(v2, v3, wh, wl);
                Oh[(row + 8) * KPW + colw] = wh;
                Ol[(row + 8) * KPW + colw] = wl;
            }
        }
    }
}

// ---------------- global mean pool ----------------
__global__ void k_pool(const float* __restrict__ h, const int* __restrict__ batch) {
    const int f = threadIdx.x;
    const int start = blockIdx.x * 256;
    if (start >= N_NODES) return;
    const int end = min(start + 256, N_NODES);
    float sum = 0.f;
    int cnt = 0;
    int cur = __ldg(&batch[start]);
    for (int i = start; i < end; i++) {
        int gid = __ldg(&batch[i]);
        if (gid != cur) {
            atomicAdd(&g_pool[cur * HID + f], sum);
            if (f == 0) atomicAdd(&g_pcnt[cur], cnt);
            sum = 0.f; cnt = 0; cur = gid;
        }
        sum += h[i * HID + f];
        cnt++;
    }
    atomicAdd(&g_pool[cur * HID + f], sum);
    if (f == 0) atomicAdd(&g_pcnt[cur], cnt);
}

// ---------------- final FC + log_softmax ----------------
__global__ void k_final(const float* __restrict__ Wfc,
                        const float* __restrict__ bfc,
                        float* __restrict__ out) {
    int g = threadIdx.x;
    if (g >= N_GRAPHS) return;
    float inv = 1.f / fmaxf((float)g_pcnt[g], 1.f);
    float logits[N_CLASSES];
    #pragma unroll
    for (int c = 0; c < N_CLASSES; c++) logits[c] = __ldg(&bfc[c]);
    for (int k = 0; k < HID; k++) {
        float p = g_pool[g * HID + k] * inv;
        #pragma unroll
        for (int c = 0; c < N_CLASSES; c++)
            logits[c] += p * __ldg(&Wfc[k * N_CLASSES + c]);
    }
    float mx = logits[0];
    #pragma unroll
    for (int c = 1; c < N_CLASSES; c++) mx = fmaxf(mx, logits[c]);
    float s = 0.f;
    #pragma unroll
    for (int c = 0; c < N_CLASSES; c++) s += expf(logits[c] - mx);
    float lse = logf(s) + mx;
    #pragma unroll
    for (int c = 0; c < N_CLASSES; c++) out[g * N_CLASSES + c] = logits[c] - lse;
}

// ---------------- launch ----------------
extern "C" void kernel_launch(void* const* d_in, const int* in_sizes, int n_in,
                              void* d_out, int out_size) {
    const float* x     = (const float*)d_in[0];
    const int*   eidx  = (const int*)d_in[1];
    const int*   batch = (const int*)d_in[2];
    const float* W1l = (const float*)d_in[3];
    const float* W1r = (const float*)d_in[4];
    const float* b1  = (const float*)d_in[5];
    const float* W2l = (const float*)d_in[6];
    const float* W2r = (const float*)d_in[7];
    const float* b2  = (const float*)d_in[8];
    const float* W3l = (const float*)d_in[9];
    const float* W3r = (const float*)d_in[10];
    const float* b3  = (const float*)d_in[11];
    const float* Wfc = (const float*)d_in[12];
    const float* bfc = (const float*)d_in[13];
    float* out = (float*)d_out;

    const int* src = eidx;
    const int* dst = eidx + N_EDGES;

    float *A32;
    unsigned *Ahh, *Ahl, *Bhh, *Bhl, *Mh, *Ml, *wph, *wpl;
    cudaGetSymbolAddress((void**)&A32, g_A32);
    cudaGetSymbolAddress((void**)&Ahh, g_Ahh);
    cudaGetSymbolAddress((void**)&Ahl, g_Ahl);
    cudaGetSymbolAddress((void**)&Bhh, g_Bhh);
    cudaGetSymbolAddress((void**)&Bhl, g_Bhl);
    cudaGetSymbolAddress((void**)&Mh,  g_Mh);
    cudaGetSymbolAddress((void**)&Ml,  g_Ml);
    cudaGetSymbolAddress((void**)&wph, g_Wph);
    cudaGetSymbolAddress((void**)&wpl, g_Wpl);

    const int GEMM_SMEM = 2 * STAGE_W * 4;
    cudaFuncSetAttribute(k_gemm_tc, cudaFuncAttributeMaxDynamicSharedMemorySize, GEMM_SMEM);

    // CSR build + weight packing
    k_zero<<<(N_NODES + 255) / 256, 256>>>();
    k_hist<<<(N_EDGES + 255) / 256, 256>>>(dst);
    k_convW<<<(2 * 128 * 128 + 255) / 256, 256>>>(W2l, W2r, W3l, W3r);
    k_scan1<<<SCAN_BLOCKS, 1024>>>();
    k_scan2<<<1, 128>>>();
    k_scan3<<<SCAN_BLOCKS, 1024>>>();
    k_scatter<<<(N_EDGES + 255) / 256, 256>>>(src, dst);

    // layer 1
    k_aggx<<<(N_NODES + 255) / 256, 256>>>(x);
    k_layer1<<<(N_NODES * KPW + 255) / 256, 256>>>(x, W1l, W1r, b1, Ahh, Ahl);

    // layer 2  (agg reads bf16-hi of h1)
    k_agg<<<(N_NODES * 32 + 255) / 256, 256>>>(Ahh, Mh, Ml);
    k_gemm_tc<<<(N_NODES + 127) / 128, 256, GEMM_SMEM>>>(Mh, Ml, Ahh, Ahl, wph, wpl, b2,
                                                         (float*)nullptr, Bhh, Bhl, 0, 1);

    // layer 3  (agg reads bf16-hi of h2)
    k_agg<<<(N_NODES * 32 + 255) / 256, 256>>>(Bhh, Mh, Ml);
    k_gemm_tc<<<(N_NODES + 127) / 128, 256, GEMM_SMEM>>>(Mh, Ml, Bhh, Bhl,
                                                         wph + 128 * 128, wpl + 128 * 128, b3,
                                                         A32, (unsigned*)nullptr, (unsigned*)nullptr, 1, 0);

    // pool + classifier
    k_pool<<<(N_NODES + 255) / 256, 128>>>(A32, batch);
    k_final<<<1, 64>>>(Wfc, bfc, out);
}

// round 9
// speedup vs baseline: 1.0037x; 1.0037x over previous
#include <cuda_runtime.h>
#include <cuda_bf16.h>

#define N_NODES  100000
#define N_EDGES  1600000
#define HID      128
#define KPW      64
#define N_GRAPHS 64
#define N_CLASSES 10
#define PADROWS  128
#define SCAN_BLOCKS 98

// ---------------- scratch ----------------
__device__ float    g_A32[(N_NODES + PADROWS) * HID];   // final layer-3 output (pool input)
__device__ unsigned g_Ahh[(N_NODES + PADROWS) * KPW];
__device__ unsigned g_Ahl[(N_NODES + PADROWS) * KPW];
__device__ unsigned g_Bhh[(N_NODES + PADROWS) * KPW];
__device__ unsigned g_Bhl[(N_NODES + PADROWS) * KPW];
__device__ unsigned g_Mh[(N_NODES + PADROWS) * KPW];
__device__ unsigned g_Ml[(N_NODES + PADROWS) * KPW];
__device__ float g_meanx[N_NODES];
__device__ int   g_cnt[N_NODES];
__device__ int   g_off[N_NODES + 1];
__device__ int   g_cur[N_NODES];
__device__ int   g_eidx[N_EDGES];
__device__ float g_pool[N_GRAPHS * HID];
__device__ int   g_pcnt[N_GRAPHS];
__device__ int   g_bsum[128];
__device__ int   g_bpre[128];
__device__ unsigned g_Wph[2 * 128 * 128];
__device__ unsigned g_Wpl[2 * 128 * 128];

// ---------------- helpers ----------------
__device__ __forceinline__ void split2(float v0, float v1, unsigned& wh, unsigned& wl) {
    __nv_bfloat162 h = __floats2bfloat162_rn(v0, v1);
    wh = *(unsigned*)&h;
    float h0f = __uint_as_float(wh << 16);
    float h1f = __uint_as_float(wh & 0xFFFF0000u);
    __nv_bfloat162 l = __floats2bfloat162_rn(v0 - h0f, v1 - h1f);
    wl = *(unsigned*)&l;
}

__device__ __forceinline__ void mma16816(float* c, const unsigned* a, const unsigned* b) {
    asm volatile(
        "mma.sync.aligned.m16n8k16.row.col.f32.bf16.bf16.f32 "
        "{%0,%1,%2,%3},{%4,%5,%6,%7},{%8,%9},{%0,%1,%2,%3};\n"
        : "+f"(c[0]), "+f"(c[1]), "+f"(c[2]), "+f"(c[3])
        : "r"(a[0]), "r"(a[1]), "r"(a[2]), "r"(a[3]), "r"(b[0]), "r"(b[1]));
}

// ---------------- zero ----------------
__global__ void k_zero() {
    int i = blockIdx.x * blockDim.x + threadIdx.x;
    if (i < N_NODES) g_cnt[i] = 0;
    if (i < N_GRAPHS * HID) g_pool[i] = 0.f;
    if (i < N_GRAPHS) g_pcnt[i] = 0;
}

__global__ void k_hist(const int* __restrict__ dst) {
    int e = blockIdx.x * blockDim.x + threadIdx.x;
    if (e < N_EDGES) atomicAdd(&g_cnt[dst[e]], 1);
}

// ---------------- multi-block scan ----------------
__global__ void k_scan1() {
    __shared__ int warpsum[32];
    const int t = threadIdx.x, lane = t & 31, wid = t >> 5;
    int i = blockIdx.x * 1024 + t;
    int v = (i < N_NODES) ? g_cnt[i] : 0;
    int x = v;
    #pragma unroll
    for (int o = 1; o < 32; o <<= 1) {
        int y = __shfl_up_sync(0xffffffff, x, o);
        if (lane >= o) x += y;
    }
    if (lane == 31) warpsum[wid] = x;
    __syncthreads();
    if (wid == 0) {
        int w = warpsum[lane];
        int xs = w;
        #pragma unroll
        for (int o = 1; o < 32; o <<= 1) {
            int y = __shfl_up_sync(0xffffffff, xs, o);
            if (lane >= o) xs += y;
        }
        warpsum[lane] = xs - w;
    }
    __syncthreads();
    int excl = warpsum[wid] + x - v;
    if (i < N_NODES) g_off[i] = excl;
    if (t == 1023) g_bsum[blockIdx.x] = excl + v;
}

__global__ void k_scan2() {
    __shared__ int wsum[4];
    const int t = threadIdx.x, lane = t & 31, wid = t >> 5;
    int v = (t < SCAN_BLOCKS) ? g_bsum[t] : 0;
    int x = v;
    #pragma unroll
    for (int o = 1; o < 32; o <<= 1) {
        int y = __shfl_up_sync(0xffffffff, x, o);
        if (lane >= o) x += y;
    }
    if (lane == 31) wsum[wid] = x;
    __syncthreads();
    int pre = 0;
    #pragma unroll
    for (int wdx = 0; wdx < 4; wdx++) if (wdx < wid) pre += wsum[wdx];
    int excl = pre + x - v;
    if (t < SCAN_BLOCKS) g_bpre[t] = excl;
    if (t == SCAN_BLOCKS - 1) g_off[N_NODES] = excl + v;
}

__global__ void k_scan3() {
    int i = blockIdx.x * 1024 + threadIdx.x;
    if (i < N_NODES) {
        int o = g_off[i] + g_bpre[blockIdx.x];
        g_off[i] = o;
        g_cur[i] = o;
    }
}

__global__ void k_scatter(const int* __restrict__ src, const int* __restrict__ dst) {
    int e = blockIdx.x * blockDim.x + threadIdx.x;
    if (e < N_EDGES) {
        int pos = atomicAdd(&g_cur[dst[e]], 1);
        g_eidx[pos] = src[e];
    }
}

// ---------------- weight convert ----------------
__global__ void k_convW(const float* __restrict__ W2l, const float* __restrict__ W2r,
                        const float* __restrict__ W3l, const float* __restrict__ W3r) {
    int idx = blockIdx.x * blockDim.x + threadIdx.x;
    if (idx >= 2 * 128 * 128) return;
    int layer = idx >> 14;
    int rem = idx & 16383;
    int n = rem >> 7;
    int kp = rem & 127;
    const float* W = (kp < 64) ? (layer ? W3l : W2l) : (layer ? W3r : W2r);
    int k = (kp < 64) ? (2 * kp) : (2 * kp - 128);
    float v0 = W[k * HID + n];
    float v1 = W[(k + 1) * HID + n];
    unsigned wh, wl;
    split2(v0, v1, wh, wl);
    g_Wph[idx] = wh;
    g_Wpl[idx] = wl;
}

// ---------------- layer-1 scalar aggregation ----------------
__global__ void k_aggx(const float* __restrict__ x) {
    int i = blockIdx.x * blockDim.x + threadIdx.x;
    if (i >= N_NODES) return;
    int b = g_off[i], e = g_off[i + 1];
    float s0 = 0.f, s1 = 0.f, s2 = 0.f, s3 = 0.f;
    int j = b;
    for (; j + 4 <= e; j += 4) {
        s0 += __ldg(&x[g_eidx[j]]);
        s1 += __ldg(&x[g_eidx[j + 1]]);
        s2 += __ldg(&x[g_eidx[j + 2]]);
        s3 += __ldg(&x[g_eidx[j + 3]]);
    }
    for (; j < e; j++) s0 += __ldg(&x[g_eidx[j]]);
    g_meanx[i] = (s0 + s1 + s2 + s3) / (float)max(e - b, 1);
}

// ---------------- layer 1: split-format output only ----------------
__global__ void k_layer1(const float* __restrict__ x,
                         const float* __restrict__ W1l,
                         const float* __restrict__ W1r,
                         const float* __restrict__ b1,
                         unsigned* __restrict__ Oh, unsigned* __restrict__ Ol) {
    int idx = blockIdx.x * blockDim.x + threadIdx.x;
    if (idx >= N_NODES * KPW) return;
    int i = idx >> 6, wq = idx & 63;
    int f0 = wq * 2;
    float mx = g_meanx[i], xi = __ldg(&x[i]);
    float v0 = fmaxf(mx * __ldg(&W1l[f0]) + xi * __ldg(&W1r[f0]) + __ldg(&b1[f0]), 0.f);
    float v1 = fmaxf(mx * __ldg(&W1l[f0 + 1]) + xi * __ldg(&W1r[f0 + 1]) + __ldg(&b1[f0 + 1]), 0.f);
    unsigned wh, wl;
    split2(v0, v1, wh, wl);
    Oh[idx] = wh;
    Ol[idx] = wl;
}

// ---------------- mean aggregation: bf16-hi gather (half traffic) -------------
__global__ void k_agg(const unsigned* __restrict__ Hh,
                      unsigned* __restrict__ Mh, unsigned* __restrict__ Ml) {
    int node = (blockIdx.x * blockDim.x + threadIdx.x) >> 5;
    int lane = threadIdx.x & 31;
    if (node >= N_NODES) return;
    int beg = g_off[node], end = g_off[node + 1];
    const uint2* hv = (const uint2*)Hh;      // 2 words = 4 features per lane
    float a0 = 0.f, a1 = 0.f, a2 = 0.f, a3 = 0.f;
    float b0 = 0.f, b1 = 0.f, b2 = 0.f, b3 = 0.f;
    int e = beg;
    for (; e + 4 <= end; e += 4) {
        int s0 = __ldg(&g_eidx[e]);
        int s1 = __ldg(&g_eidx[e + 1]);
        int s2 = __ldg(&g_eidx[e + 2]);
        int s3 = __ldg(&g_eidx[e + 3]);
        uint2 v0 = __ldg(&hv[s0 * 32 + lane]);
        uint2 v1 = __ldg(&hv[s1 * 32 + lane]);
        uint2 v2 = __ldg(&hv[s2 * 32 + lane]);
        uint2 v3 = __ldg(&hv[s3 * 32 + lane]);
        a0 += __uint_as_float(v0.x << 16);  a1 += __uint_as_float(v0.x & 0xFFFF0000u);
        a2 += __uint_as_float(v0.y << 16);  a3 += __uint_as_float(v0.y & 0xFFFF0000u);
        b0 += __uint_as_float(v1.x << 16);  b1 += __uint_as_float(v1.x & 0xFFFF0000u);
        b2 += __uint_as_float(v1.y << 16);  b3 += __uint_as_float(v1.y & 0xFFFF0000u);
        a0 += __uint_as_float(v2.x << 16);  a1 += __uint_as_float(v2.x & 0xFFFF0000u);
        a2 += __uint_as_float(v2.y << 16);  a3 += __uint_as_float(v2.y & 0xFFFF0000u);
        b0 += __uint_as_float(v3.x << 16);  b1 += __uint_as_float(v3.x & 0xFFFF0000u);
        b2 += __uint_as_float(v3.y << 16);  b3 += __uint_as_float(v3.y & 0xFFFF0000u);
    }
    for (; e < end; e++) {
        int s = __ldg(&g_eidx[e]);
        uint2 v = __ldg(&hv[s * 32 + lane]);
        a0 += __uint_as_float(v.x << 16);  a1 += __uint_as_float(v.x & 0xFFFF0000u);
        a2 += __uint_as_float(v.y << 16);  a3 += __uint_as_float(v.y & 0xFFFF0000u);
    }
    float inv = 1.f / (float)max(end - beg, 1);
    unsigned wh0, wl0, wh1, wl1;
    split2((a0 + b0) * inv, (a1 + b1) * inv, wh0, wl0);
    split2((a2 + b2) * inv, (a3 + b3) * inv, wh1, wl1);
    *(uint2*)&Mh[node * KPW + lane * 2] = make_uint2(wh0, wh1);
    *(uint2*)&Ml[node * KPW + lane * 2] = make_uint2(wl0, wl1);
}

// ---------------- tensor-core GEMM, conversion-free, 2-stage cp.async ---------
#define TSTR 20
#define PART_W 2560
#define STAGE_W (4 * PART_W)
__global__ __launch_bounds__(256, 2) void k_gemm_tc(
    const unsigned* __restrict__ Mh_, const unsigned* __restrict__ Ml_,
    const unsigned* __restrict__ Hh_, const unsigned* __restrict__ Hl_,
    const unsigned* __restrict__ Wph, const unsigned* __restrict__ Wpl,
    const float* __restrict__ bias,
    float* __restrict__ O32,
    unsigned* __restrict__ Oh, unsigned* __restrict__ Ol,
    int storeF32, int storeSplit)
{
    extern __shared__ unsigned sm[];
    const int t = threadIdx.x, lane = t & 31, w = t >> 5;
    const int wm = w >> 2, wn = w & 3;
    const int g = lane >> 2, tid4 = lane & 3;
    const int m0 = blockIdx.x * 128;

    auto fill = [&](int stage, int kb) {
        const unsigned* Ah_ = (kb < 4) ? Mh_ : Hh_;
        const unsigned* Al_ = (kb < 4) ? Ml_ : Hl_;
        const int koff = (kb & 3) * 16;
        const unsigned base = stage * STAGE_W;
        #pragma unroll
        for (int i = 0; i < 8; i++) {
            int id = t + 256 * i;
            int part = id >> 9;
            int rem = id & 511;
            int r = rem >> 2, wq = (rem & 3) * 4;
            const unsigned* src;
            if (part == 0)      src = Ah_ + (m0 + r) * KPW + koff + wq;
            else if (part == 1) src = Al_ + (m0 + r) * KPW + koff + wq;
            else if (part == 2) src = Wph + r * 128 + kb * 16 + wq;
            else                src = Wpl + r * 128 + kb * 16 + wq;
            unsigned daddr = (unsigned)__cvta_generic_to_shared(sm + base + part * PART_W + r * TSTR + wq);
            asm volatile("cp.async.cg.shared.global [%0],[%1],16;\n" :: "r"(daddr), "l"(src));
        }
        asm volatile("cp.async.commit_group;\n");
    };

    float acc[4][4][4];
    #pragma unroll
    for (int a = 0; a < 4; a++)
        #pragma unroll
        for (int b = 0; b < 4; b++)
            #pragma unroll
            for (int c = 0; c < 4; c++) acc[a][b][c] = 0.f;

    fill(0, 0);
    fill(1, 1);

    for (int kb = 0; kb < 8; kb++) {
        if (kb < 7) asm volatile("cp.async.wait_group 1;\n");
        else        asm volatile("cp.async.wait_group 0;\n");
        __syncthreads();
        const unsigned base = (kb & 1) * STAGE_W;
        const unsigned* Ash = sm + base;
        const unsigned* Asl = sm + base + PART_W;
        const unsigned* Wsh = sm + base + 2 * PART_W;
        const unsigned* Wsl = sm + base + 3 * PART_W;
        #pragma unroll
        for (int ks = 0; ks < 2; ks++) {
            const int kp0 = ks * 8 + tid4;
            unsigned ah[4][4], al[4][4], bh[4][2], bl[4][2];
            #pragma unroll
            for (int mt = 0; mt < 4; mt++) {
                int r = wm * 64 + mt * 16 + g;
                ah[mt][0] = Ash[r * TSTR + kp0];       ah[mt][1] = Ash[(r + 8) * TSTR + kp0];
                ah[mt][2] = Ash[r * TSTR + kp0 + 4];   ah[mt][3] = Ash[(r + 8) * TSTR + kp0 + 4];
                al[mt][0] = Asl[r * TSTR + kp0];       al[mt][1] = Asl[(r + 8) * TSTR + kp0];
                al[mt][2] = Asl[r * TSTR + kp0 + 4];   al[mt][3] = Asl[(r + 8) * TSTR + kp0 + 4];
            }
            #pragma unroll
            for (int nt = 0; nt < 4; nt++) {
                int n = wn * 32 + nt * 8 + g;
                bh[nt][0] = Wsh[n * TSTR + kp0]; bh[nt][1] = Wsh[n * TSTR + kp0 + 4];
                bl[nt][0] = Wsl[n * TSTR + kp0]; bl[nt][1] = Wsl[n * TSTR + kp0 + 4];
            }
            #pragma unroll
            for (int mt = 0; mt < 4; mt++)
                #pragma unroll
                for (int nt = 0; nt < 4; nt++) {
                    mma16816(acc[mt][nt], ah[mt], bh[nt]);
                    mma16816(acc[mt][nt], ah[mt], bl[nt]);
                    mma16816(acc[mt][nt], al[mt], bh[nt]);
                }
        }
        __syncthreads();
        if (kb + 2 < 8) fill(kb & 1, kb + 2);
    }

    #pragma unroll
    for (int nt = 0; nt < 4; nt++) {
        int colw = wn * 16 + nt * 4 + tid4;
        int col = colw * 2;
        float b0 = __ldg(&bias[col]), b1 = __ldg(&bias[col + 1]);
        #pragma unroll
        for (int mt = 0; mt < 4; mt++) {
            int row = m0 + wm * 64 + mt * 16 + g;
            float v0 = fmaxf(acc[mt][nt][0] + b0, 0.f);
            float v1 = fmaxf(acc[mt][nt][1] + b1, 0.f);
            float v2 = fmaxf(acc[mt][nt][2] + b0, 0.f);
            float v3 = fmaxf(acc[mt][nt][3] + b1, 0.f);
            if (storeF32) {
                *(float2*)&O32[row * HID + col] = make_float2(v0, v1);
                *(float2*)&O32[(row + 8) * HID + col] = make_float2(v2, v3);
            }
            if (storeSplit) {
                unsigned wh, wl;
                split2(v0, v1, wh, wl);
                Oh[row * KPW + colw] = wh;
                Ol[row * KPW + colw] = wl;
                split2(v2, v3, wh, wl);
                Oh[(row + 8) * KPW + colw] = wh;
                Ol[(row + 8) * KPW + colw] = wl;
            }
        }
    }
}

// ---------------- global mean pool ----------------
__global__ void k_pool(const float* __restrict__ h, const int* __restrict__ batch) {
    const int f = threadIdx.x;
    const int start = blockIdx.x * 256;
    if (start >= N_NODES) return;
    const int end = min(start + 256, N_NODES);
    float sum = 0.f;
    int cnt = 0;
    int cur = __ldg(&batch[start]);
    for (int i = start; i < end; i++) {
        int gid = __ldg(&batch[i]);
        if (gid != cur) {
            atomicAdd(&g_pool[cur * HID + f], sum);
            if (f == 0) atomicAdd(&g_pcnt[cur], cnt);
            sum = 0.f; cnt = 0; cur = gid;
        }
        sum += h[i * HID + f];
        cnt++;
    }
    atomicAdd(&g_pool[cur * HID + f], sum);
    if (f == 0) atomicAdd(&g_pcnt[cur], cnt);
}

// ---------------- final FC + log_softmax ----------------
__global__ void k_final(const float* __restrict__ Wfc,
                        const float* __restrict__ bfc,
                        float* __restrict__ out) {
    int g = threadIdx.x;
    if (g >= N_GRAPHS) return;
    float inv = 1.f / fmaxf((float)g_pcnt[g], 1.f);
    float logits[N_CLASSES];
    #pragma unroll
    for (int c = 0; c < N_CLASSES; c++) logits[c] = __ldg(&bfc[c]);
    for (int k = 0; k < HID; k++) {
        float p = g_pool[g * HID + k] * inv;
        #pragma unroll
        for (int c = 0; c < N_CLASSES; c++)
            logits[c] += p * __ldg(&Wfc[k * N_CLASSES + c]);
    }
    float mx = logits[0];
    #pragma unroll
    for (int c = 1; c < N_CLASSES; c++) mx = fmaxf(mx, logits[c]);
    float s = 0.f;
    #pragma unroll
    for (int c = 0; c < N_CLASSES; c++) s += expf(logits[c] - mx);
    float lse = logf(s) + mx;
    #pragma unroll
    for (int c = 0; c < N_CLASSES; c++) out[g * N_CLASSES + c] = logits[c] - lse;
}

// ---------------- launch ----------------
extern "C" void kernel_launch(void* const* d_in, const int* in_sizes, int n_in,
                              void* d_out, int out_size) {
    const float* x     = (const float*)d_in[0];
    const int*   eidx  = (const int*)d_in[1];
    const int*   batch = (const int*)d_in[2];
    const float* W1l = (const float*)d_in[3];
    const float* W1r = (const float*)d_in[4];
    const float* b1  = (const float*)d_in[5];
    const float* W2l = (const float*)d_in[6];
    const float* W2r = (const float*)d_in[7];
    const float* b2  = (const float*)d_in[8];
    const float* W3l = (const float*)d_in[9];
    const float* W3r = (const float*)d_in[10];
    const float* b3  = (const float*)d_in[11];
    const float* Wfc = (const float*)d_in[12];
    const float* bfc = (const float*)d_in[13];
    float* out = (float*)d_out;

    const int* src = eidx;
    const int* dst = eidx + N_EDGES;

    float *A32;
    unsigned *Ahh, *Ahl, *Bhh, *Bhl, *Mh, *Ml, *wph, *wpl;
    cudaGetSymbolAddress((void**)&A32, g_A32);
    cudaGetSymbolAddress((void**)&Ahh, g_Ahh);
    cudaGetSymbolAddress((void**)&Ahl, g_Ahl);
    cudaGetSymbolAddress((void**)&Bhh, g_Bhh);
    cudaGetSymbolAddress((void**)&Bhl, g_Bhl);
    cudaGetSymbolAddress((void**)&Mh,  g_Mh);
    cudaGetSymbolAddress((void**)&Ml,  g_Ml);
    cudaGetSymbolAddress((void**)&wph, g_Wph);
    cudaGetSymbolAddress((void**)&wpl, g_Wpl);

    const int GEMM_SMEM = 2 * STAGE_W * 4;
    cudaFuncSetAttribute(k_gemm_tc, cudaFuncAttributeMaxDynamicSharedMemorySize, GEMM_SMEM);

    // CSR build + weight packing
    k_zero<<<(N_NODES + 255) / 256, 256>>>();
    k_hist<<<(N_EDGES + 255) / 256, 256>>>(dst);
    k_convW<<<(2 * 128 * 128 + 255) / 256, 256>>>(W2l, W2r, W3l, W3r);
    k_scan1<<<SCAN_BLOCKS, 1024>>>();
    k_scan2<<<1, 128>>>();
    k_scan3<<<SCAN_BLOCKS, 1024>>>();
    k_scatter<<<(N_EDGES + 255) / 256, 256>>>(src, dst);

    // layer 1
    k_aggx<<<(N_NODES + 255) / 256, 256>>>(x);
    k_layer1<<<(N_NODES * KPW + 255) / 256, 256>>>(x, W1l, W1r, b1, Ahh, Ahl);

    // layer 2  (agg reads bf16-hi of h1)
    k_agg<<<(N_NODES * 32 + 255) / 256, 256>>>(Ahh, Mh, Ml);
    k_gemm_tc<<<(N_NODES + 127) / 128, 256, GEMM_SMEM>>>(Mh, Ml, Ahh, Ahl, wph, wpl, b2,
                                                         (float*)nullptr, Bhh, Bhl, 0, 1);

    // layer 3  (agg reads bf16-hi of h2)
    k_agg<<<(N_NODES * 32 + 255) / 256, 256>>>(Bhh, Mh, Ml);
    k_gemm_tc<<<(N_NODES + 127) / 128, 256, GEMM_SMEM>>>(Mh, Ml, Bhh, Bhl,
                                                         wph + 128 * 128, wpl + 128 * 128, b3,
                                                         A32, (unsigned*)nullptr, (unsigned*)nullptr, 1, 0);

    // pool + classifier
    k_pool<<<(N_NODES + 255) / 256, 128>>>(A32, batch);
    k_final<<<1, 64>>>(Wfc, bfc, out);
}

// round 10
// speedup vs baseline: 1.0219x; 1.0182x over previous
#include <cuda_runtime.h>
#include <cuda_bf16.h>

#define N_NODES  100000
#define N_EDGES  1600000
#define HID      128
#define KPW      64
#define N_GRAPHS 64
#define N_CLASSES 10
#define PADROWS  128
#define SCAN_BLOCKS 98

// ---------------- scratch ----------------
__device__ float    g_A32[(N_NODES + PADROWS) * HID];   // final layer-3 output (pool input)
__device__ unsigned g_Ahh[(N_NODES + PADROWS) * KPW];
__device__ unsigned g_Ahl[(N_NODES + PADROWS) * KPW];
__device__ unsigned g_Bhh[(N_NODES + PADROWS) * KPW];
__device__ unsigned g_Bhl[(N_NODES + PADROWS) * KPW];
__device__ unsigned g_Mh[(N_NODES + PADROWS) * KPW];
__device__ unsigned g_Ml[(N_NODES + PADROWS) * KPW];
__device__ float g_meanx[N_NODES];
__device__ int   g_cnt[N_NODES];
__device__ int   g_off[N_NODES + 1];
__device__ int   g_cur[N_NODES];
__device__ int   g_eidx[N_EDGES];
__device__ float g_pool[N_GRAPHS * HID];
__device__ int   g_pcnt[N_GRAPHS];
__device__ int   g_bsum[128];
__device__ int   g_bpre[128];
__device__ unsigned g_Wph[2 * 128 * 128];
__device__ unsigned g_Wpl[2 * 128 * 128];

// ---------------- helpers ----------------
__device__ __forceinline__ void split2(float v0, float v1, unsigned& wh, unsigned& wl) {
    __nv_bfloat162 h = __floats2bfloat162_rn(v0, v1);
    wh = *(unsigned*)&h;
    float h0f = __uint_as_float(wh << 16);
    float h1f = __uint_as_float(wh & 0xFFFF0000u);
    __nv_bfloat162 l = __floats2bfloat162_rn(v0 - h0f, v1 - h1f);
    wl = *(unsigned*)&l;
}

__device__ __forceinline__ void mma16816(float* c, const unsigned* a, const unsigned* b) {
    asm volatile(
        "mma.sync.aligned.m16n8k16.row.col.f32.bf16.bf16.f32 "
        "{%0,%1,%2,%3},{%4,%5,%6,%7},{%8,%9},{%0,%1,%2,%3};\n"
        : "+f"(c[0]), "+f"(c[1]), "+f"(c[2]), "+f"(c[3])
        : "r"(a[0]), "r"(a[1]), "r"(a[2]), "r"(a[3]), "r"(b[0]), "r"(b[1]));
}

// ---------------- zero ----------------
__global__ void k_zero() {
    int i = blockIdx.x * blockDim.x + threadIdx.x;
    if (i < N_NODES) g_cnt[i] = 0;
    if (i < N_GRAPHS * HID) g_pool[i] = 0.f;
    if (i < N_GRAPHS) g_pcnt[i] = 0;
}

__global__ void k_hist(const int* __restrict__ dst) {
    int e = blockIdx.x * blockDim.x + threadIdx.x;
    if (e < N_EDGES) atomicAdd(&g_cnt[dst[e]], 1);
}

// ---------------- multi-block scan ----------------
__global__ void k_scan1() {
    __shared__ int warpsum[32];
    const int t = threadIdx.x, lane = t & 31, wid = t >> 5;
    int i = blockIdx.x * 1024 + t;
    int v = (i < N_NODES) ? g_cnt[i] : 0;
    int x = v;
    #pragma unroll
    for (int o = 1; o < 32; o <<= 1) {
        int y = __shfl_up_sync(0xffffffff, x, o);
        if (lane >= o) x += y;
    }
    if (lane == 31) warpsum[wid] = x;
    __syncthreads();
    if (wid == 0) {
        int w = warpsum[lane];
        int xs = w;
        #pragma unroll
        for (int o = 1; o < 32; o <<= 1) {
            int y = __shfl_up_sync(0xffffffff, xs, o);
            if (lane >= o) xs += y;
        }
        warpsum[lane] = xs - w;
    }
    __syncthreads();
    int excl = warpsum[wid] + x - v;
    if (i < N_NODES) g_off[i] = excl;
    if (t == 1023) g_bsum[blockIdx.x] = excl + v;
}

__global__ void k_scan2() {
    __shared__ int wsum[4];
    const int t = threadIdx.x, lane = t & 31, wid = t >> 5;
    int v = (t < SCAN_BLOCKS) ? g_bsum[t] : 0;
    int x = v;
    #pragma unroll
    for (int o = 1; o < 32; o <<= 1) {
        int y = __shfl_up_sync(0xffffffff, x, o);
        if (lane >= o) x += y;
    }
    if (lane == 31) wsum[wid] = x;
    __syncthreads();
    int pre = 0;
    #pragma unroll
    for (int wdx = 0; wdx < 4; wdx++) if (wdx < wid) pre += wsum[wdx];
    int excl = pre + x - v;
    if (t < SCAN_BLOCKS) g_bpre[t] = excl;
    if (t == SCAN_BLOCKS - 1) g_off[N_NODES] = excl + v;
}

__global__ void k_scan3() {
    int i = blockIdx.x * 1024 + threadIdx.x;
    if (i < N_NODES) {
        int o = g_off[i] + g_bpre[blockIdx.x];
        g_off[i] = o;
        g_cur[i] = o;
    }
}

__global__ void k_scatter(const int* __restrict__ src, const int* __restrict__ dst) {
    int e = blockIdx.x * blockDim.x + threadIdx.x;
    if (e < N_EDGES) {
        int pos = atomicAdd(&g_cur[dst[e]], 1);
        g_eidx[pos] = src[e];
    }
}

// ---------------- weight convert ----------------
__global__ void k_convW(const float* __restrict__ W2l, const float* __restrict__ W2r,
                        const float* __restrict__ W3l, const float* __restrict__ W3r) {
    int idx = blockIdx.x * blockDim.x + threadIdx.x;
    if (idx >= 2 * 128 * 128) return;
    int layer = idx >> 14;
    int rem = idx & 16383;
    int n = rem >> 7;
    int kp = rem & 127;
    const float* W = (kp < 64) ? (layer ? W3l : W2l) : (layer ? W3r : W2r);
    int k = (kp < 64) ? (2 * kp) : (2 * kp - 128);
    float v0 = W[k * HID + n];
    float v1 = W[(k + 1) * HID + n];
    unsigned wh, wl;
    split2(v0, v1, wh, wl);
    g_Wph[idx] = wh;
    g_Wpl[idx] = wl;
}

// ---------------- layer-1 scalar aggregation ----------------
__global__ void k_aggx(const float* __restrict__ x) {
    int i = blockIdx.x * blockDim.x + threadIdx.x;
    if (i >= N_NODES) return;
    int b = g_off[i], e = g_off[i + 1];
    float s0 = 0.f, s1 = 0.f, s2 = 0.f, s3 = 0.f;
    int j = b;
    for (; j + 4 <= e; j += 4) {
        s0 += __ldg(&x[g_eidx[j]]);
        s1 += __ldg(&x[g_eidx[j + 1]]);
        s2 += __ldg(&x[g_eidx[j + 2]]);
        s3 += __ldg(&x[g_eidx[j + 3]]);
    }
    for (; j < e; j++) s0 += __ldg(&x[g_eidx[j]]);
    g_meanx[i] = (s0 + s1 + s2 + s3) / (float)max(e - b, 1);
}

// ---------------- layer 1: split-format output only ----------------
__global__ void k_layer1(const float* __restrict__ x,
                         const float* __restrict__ W1l,
                         const float* __restrict__ W1r,
                         const float* __restrict__ b1,
                         unsigned* __restrict__ Oh, unsigned* __restrict__ Ol) {
    int idx = blockIdx.x * blockDim.x + threadIdx.x;
    if (idx >= N_NODES * KPW) return;
    int i = idx >> 6, wq = idx & 63;
    int f0 = wq * 2;
    float mx = g_meanx[i], xi = __ldg(&x[i]);
    float v0 = fmaxf(mx * __ldg(&W1l[f0]) + xi * __ldg(&W1r[f0]) + __ldg(&b1[f0]), 0.f);
    float v1 = fmaxf(mx * __ldg(&W1l[f0 + 1]) + xi * __ldg(&W1r[f0 + 1]) + __ldg(&b1[f0 + 1]), 0.f);
    unsigned wh, wl;
    split2(v0, v1, wh, wl);
    Oh[idx] = wh;
    Ol[idx] = wl;
}

// ---------------- mean aggregation: bf16-hi gather (half traffic) -------------
__global__ void k_agg(const unsigned* __restrict__ Hh,
                      unsigned* __restrict__ Mh, unsigned* __restrict__ Ml) {
    int node = (blockIdx.x * blockDim.x + threadIdx.x) >> 5;
    int lane = threadIdx.x & 31;
    if (node >= N_NODES) return;
    int beg = g_off[node], end = g_off[node + 1];
    const uint2* hv = (const uint2*)Hh;      // 2 words = 4 features per lane
    float a0 = 0.f, a1 = 0.f, a2 = 0.f, a3 = 0.f;
    float b0 = 0.f, b1 = 0.f, b2 = 0.f, b3 = 0.f;
    int e = beg;
    for (; e + 4 <= end; e += 4) {
        int s0 = __ldg(&g_eidx[e]);
        int s1 = __ldg(&g_eidx[e + 1]);
        int s2 = __ldg(&g_eidx[e + 2]);
        int s3 = __ldg(&g_eidx[e + 3]);
        uint2 v0 = __ldg(&hv[s0 * 32 + lane]);
        uint2 v1 = __ldg(&hv[s1 * 32 + lane]);
        uint2 v2 = __ldg(&hv[s2 * 32 + lane]);
        uint2 v3 = __ldg(&hv[s3 * 32 + lane]);
        a0 += __uint_as_float(v0.x << 16);  a1 += __uint_as_float(v0.x & 0xFFFF0000u);
        a2 += __uint_as_float(v0.y << 16);  a3 += __uint_as_float(v0.y & 0xFFFF0000u);
        b0 += __uint_as_float(v1.x << 16);  b1 += __uint_as_float(v1.x & 0xFFFF0000u);
        b2 += __uint_as_float(v1.y << 16);  b3 += __uint_as_float(v1.y & 0xFFFF0000u);
        a0 += __uint_as_float(v2.x << 16);  a1 += __uint_as_float(v2.x & 0xFFFF0000u);
        a2 += __uint_as_float(v2.y << 16);  a3 += __uint_as_float(v2.y & 0xFFFF0000u);
        b0 += __uint_as_float(v3.x << 16);  b1 += __uint_as_float(v3.x & 0xFFFF0000u);
        b2 += __uint_as_float(v3.y << 16);  b3 += __uint_as_float(v3.y & 0xFFFF0000u);
    }
    for (; e < end; e++) {
        int s = __ldg(&g_eidx[e]);
        uint2 v = __ldg(&hv[s * 32 + lane]);
        a0 += __uint_as_float(v.x << 16);  a1 += __uint_as_float(v.x & 0xFFFF0000u);
        a2 += __uint_as_float(v.y << 16);  a3 += __uint_as_float(v.y & 0xFFFF0000u);
    }
    float inv = 1.f / (float)max(end - beg, 1);
    unsigned wh0, wl0, wh1, wl1;
    split2((a0 + b0) * inv, (a1 + b1) * inv, wh0, wl0);
    split2((a2 + b2) * inv, (a3 + b3) * inv, wh1, wl1);
    *(uint2*)&Mh[node * KPW + lane * 2] = make_uint2(wh0, wh1);
    *(uint2*)&Ml[node * KPW + lane * 2] = make_uint2(wl0, wl1);
}

// ---------------- tensor-core GEMM, conversion-free, 2-stage cp.async ---------
#define TSTR 20
#define PART_W 2560
#define STAGE_W (4 * PART_W)
__global__ __launch_bounds__(256, 2) void k_gemm_tc(
    const unsigned* __restrict__ Mh_, const unsigned* __restrict__ Ml_,
    const unsigned* __restrict__ Hh_, const unsigned* __restrict__ Hl_,
    const unsigned* __restrict__ Wph, const unsigned* __restrict__ Wpl,
    const float* __restrict__ bias,
    float* __restrict__ O32,
    unsigned* __restrict__ Oh, unsigned* __restrict__ Ol,
    int storeF32, int storeSplit)
{
    extern __shared__ unsigned sm[];
    const int t = threadIdx.x, lane = t & 31, w = t >> 5;
    const int wm = w >> 2, wn = w & 3;
    const int g = lane >> 2, tid4 = lane & 3;
    const int m0 = blockIdx.x * 128;

    auto fill = [&](int stage, int kb) {
        const unsigned* Ah_ = (kb < 4) ? Mh_ : Hh_;
        const unsigned* Al_ = (kb < 4) ? Ml_ : Hl_;
        const int koff = (kb & 3) * 16;
        const unsigned base = stage * STAGE_W;
        #pragma unroll
        for (int i = 0; i < 8; i++) {
            int id = t + 256 * i;
            int part = id >> 9;
            int rem = id & 511;
            int r = rem >> 2, wq = (rem & 3) * 4;
            const unsigned* src;
            if (part == 0)      src = Ah_ + (m0 + r) * KPW + koff + wq;
            else if (part == 1) src = Al_ + (m0 + r) * KPW + koff + wq;
            else if (part == 2) src = Wph + r * 128 + kb * 16 + wq;
            else                src = Wpl + r * 128 + kb * 16 + wq;
            unsigned daddr = (unsigned)__cvta_generic_to_shared(sm + base + part * PART_W + r * TSTR + wq);
            asm volatile("cp.async.cg.shared.global [%0],[%1],16;\n" :: "r"(daddr), "l"(src));
        }
        asm volatile("cp.async.commit_group;\n");
    };

    float acc[4][4][4];
    #pragma unroll
    for (int a = 0; a < 4; a++)
        #pragma unroll
        for (int b = 0; b < 4; b++)
            #pragma unroll
            for (int c = 0; c < 4; c++) acc[a][b][c] = 0.f;

    fill(0, 0);
    fill(1, 1);

    for (int kb = 0; kb < 8; kb++) {
        if (kb < 7) asm volatile("cp.async.wait_group 1;\n");
        else        asm volatile("cp.async.wait_group 0;\n");
        __syncthreads();
        const unsigned base = (kb & 1) * STAGE_W;
        const unsigned* Ash = sm + base;
        const unsigned* Asl = sm + base + PART_W;
        const unsigned* Wsh = sm + base + 2 * PART_W;
        const unsigned* Wsl = sm + base + 3 * PART_W;
        #pragma unroll
        for (int ks = 0; ks < 2; ks++) {
            const int kp0 = ks * 8 + tid4;
            unsigned ah[4][4], al[4][4], bh[4][2], bl[4][2];
            #pragma unroll
            for (int mt = 0; mt < 4; mt++) {
                int r = wm * 64 + mt * 16 + g;
                ah[mt][0] = Ash[r * TSTR + kp0];       ah[mt][1] = Ash[(r + 8) * TSTR + kp0];
                ah[mt][2] = Ash[r * TSTR + kp0 + 4];   ah[mt][3] = Ash[(r + 8) * TSTR + kp0 + 4];
                al[mt][0] = Asl[r * TSTR + kp0];       al[mt][1] = Asl[(r + 8) * TSTR + kp0];
                al[mt][2] = Asl[r * TSTR + kp0 + 4];   al[mt][3] = Asl[(r + 8) * TSTR + kp0 + 4];
            }
            #pragma unroll
            for (int nt = 0; nt < 4; nt++) {
                int n = wn * 32 + nt * 8 + g;
                bh[nt][0] = Wsh[n * TSTR + kp0]; bh[nt][1] = Wsh[n * TSTR + kp0 + 4];
                bl[nt][0] = Wsl[n * TSTR + kp0]; bl[nt][1] = Wsl[n * TSTR + kp0 + 4];
            }
            #pragma unroll
            for (int mt = 0; mt < 4; mt++)
                #pragma unroll
                for (int nt = 0; nt < 4; nt++) {
                    mma16816(acc[mt][nt], ah[mt], bh[nt]);
                    mma16816(acc[mt][nt], ah[mt], bl[nt]);
                    mma16816(acc[mt][nt], al[mt], bh[nt]);
                }
        }
        __syncthreads();
        if (kb + 2 < 8) fill(kb & 1, kb + 2);
    }

    #pragma unroll
    for (int nt = 0; nt < 4; nt++) {
        int colw = wn * 16 + nt * 4 + tid4;
        int col = colw * 2;
        float b0 = __ldg(&bias[col]), b1 = __ldg(&bias[col + 1]);
        #pragma unroll
        for (int mt = 0; mt < 4; mt++) {
            int row = m0 + wm * 64 + mt * 16 + g;
            float v0 = fmaxf(acc[mt][nt][0] + b0, 0.f);
            float v1 = fmaxf(acc[mt][nt][1] + b1, 0.f);
            float v2 = fmaxf(acc[mt][nt][2] + b0, 0.f);
            float v3 = fmaxf(acc[mt][nt][3] + b1, 0.f);
            if (storeF32) {
                *(float2*)&O32[row * HID + col] = make_float2(v0, v1);
                *(float2*)&O32[(row + 8) * HID + col] = make_float2(v2, v3);
            }
            if (storeSplit) {
                unsigned wh, wl;
                split2(v0, v1, wh, wl);
                Oh[row * KPW + colw] = wh;
                Ol[row * KPW + colw] = wl;
                split2(v2, v3, wh, wl);
                Oh[(row + 8) * KPW + colw] = wh;
                Ol[(row + 8) * KPW + colw] = wl;
            }
        }
    }
}

// ---------------- global mean pool ----------------
__global__ void k_pool(const float* __restrict__ h, const int* __restrict__ batch) {
    const int f = threadIdx.x;
    const int start = blockIdx.x * 256;
    if (start >= N_NODES) return;
    const int end = min(start + 256, N_NODES);
    float sum = 0.f;
    int cnt = 0;
    int cur = __ldg(&batch[start]);
    for (int i = start; i < end; i++) {
        int gid = __ldg(&batch[i]);
        if (gid != cur) {
            atomicAdd(&g_pool[cur * HID + f], sum);
            if (f == 0) atomicAdd(&g_pcnt[cur], cnt);
            sum = 0.f; cnt = 0; cur = gid;
        }
        sum += h[i * HID + f];
        cnt++;
    }
    atomicAdd(&g_pool[cur * HID + f], sum);
    if (f == 0) atomicAdd(&g_pcnt[cur], cnt);
}

// ---------------- final FC + log_softmax ----------------
__global__ void k_final(const float* __restrict__ Wfc,
                        const float* __restrict__ bfc,
                        float* __restrict__ out) {
    int g = threadIdx.x;
    if (g >= N_GRAPHS) return;
    float inv = 1.f / fmaxf((float)g_pcnt[g], 1.f);
    float logits[N_CLASSES];
    #pragma unroll
    for (int c = 0; c < N_CLASSES; c++) logits[c] = __ldg(&bfc[c]);
    for (int k = 0; k < HID; k++) {
        float p = g_pool[g * HID + k] * inv;
        #pragma unroll
        for (int c = 0; c < N_CLASSES; c++)
            logits[c] += p * __ldg(&Wfc[k * N_CLASSES + c]);
    }
    float mx = logits[0];
    #pragma unroll
    for (int c = 1; c < N_CLASSES; c++) mx = fmaxf(mx, logits[c]);
    float s = 0.f;
    #pragma unroll
    for (int c = 0; c < N_CLASSES; c++) s += expf(logits[c] - mx);
    float lse = logf(s) + mx;
    #pragma unroll
    for (int c = 0; c < N_CLASSES; c++) out[g * N_CLASSES + c] = logits[c] - lse;
}

// ---------------- launch ----------------
extern "C" void kernel_launch(void* const* d_in, const int* in_sizes, int n_in,
                              void* d_out, int out_size) {
    const float* x     = (const float*)d_in[0];
    const int*   eidx  = (const int*)d_in[1];
    const int*   batch = (const int*)d_in[2];
    const float* W1l = (const float*)d_in[3];
    const float* W1r = (const float*)d_in[4];
    const float* b1  = (const float*)d_in[5];
    const float* W2l = (const float*)d_in[6];
    const float* W2r = (const float*)d_in[7];
    const float* b2  = (const float*)d_in[8];
    const float* W3l = (const float*)d_in[9];
    const float* W3r = (const float*)d_in[10];
    const float* b3  = (const float*)d_in[11];
    const float* Wfc = (const float*)d_in[12];
    const float* bfc = (const float*)d_in[13];
    float* out = (float*)d_out;

    const int* src = eidx;
    const int* dst = eidx + N_EDGES;

    float *A32;
    unsigned *Ahh, *Ahl, *Bhh, *Bhl, *Mh, *Ml, *wph, *wpl;
    cudaGetSymbolAddress((void**)&A32, g_A32);
    cudaGetSymbolAddress((void**)&Ahh, g_Ahh);
    cudaGetSymbolAddress((void**)&Ahl, g_Ahl);
    cudaGetSymbolAddress((void**)&Bhh, g_Bhh);
    cudaGetSymbolAddress((void**)&Bhl, g_Bhl);
    cudaGetSymbolAddress((void**)&Mh,  g_Mh);
    cudaGetSymbolAddress((void**)&Ml,  g_Ml);
    cudaGetSymbolAddress((void**)&wph, g_Wph);
    cudaGetSymbolAddress((void**)&wpl, g_Wpl);

    const int GEMM_SMEM = 2 * STAGE_W * 4;
    cudaFuncSetAttribute(k_gemm_tc, cudaFuncAttributeMaxDynamicSharedMemorySize, GEMM_SMEM);

    // CSR build + weight packing
    k_zero<<<(N_NODES + 255) / 256, 256>>>();
    k_hist<<<(N_EDGES + 255) / 256, 256>>>(dst);
    k_convW<<<(2 * 128 * 128 + 255) / 256, 256>>>(W2l, W2r, W3l, W3r);
    k_scan1<<<SCAN_BLOCKS, 1024>>>();
    k_scan2<<<1, 128>>>();
    k_scan3<<<SCAN_BLOCKS, 1024>>>();
    k_scatter<<<(N_EDGES + 255) / 256, 256>>>(src, dst);

    // layer 1
    k_aggx<<<(N_NODES + 255) / 256, 256>>>(x);
    k_layer1<<<(N_NODES * KPW + 255) / 256, 256>>>(x, W1l, W1r, b1, Ahh, Ahl);

    // layer 2  (agg reads bf16-hi of h1)
    k_agg<<<(N_NODES * 32 + 255) / 256, 256>>>(Ahh, Mh, Ml);
    k_gemm_tc<<<(N_NODES + 127) / 128, 256, GEMM_SMEM>>>(Mh, Ml, Ahh, Ahl, wph, wpl, b2,
                                                         (float*)nullptr, Bhh, Bhl, 0, 1);

    // layer 3  (agg reads bf16-hi of h2)
    k_agg<<<(N_NODES * 32 + 255) / 256, 256>>>(Bhh, Mh, Ml);
    k_gemm_tc<<<(N_NODES + 127) / 128, 256, GEMM_SMEM>>>(Mh, Ml, Bhh, Bhl,
                                                         wph + 128 * 128, wpl + 128 * 128, b3,
                                                         A32, (unsigned*)nullptr, (unsigned*)nullptr, 1, 0);

    // pool + classifier
    k_pool<<<(N_NODES + 255) / 256, 128>>>(A32, batch);
    k_final<<<1, 64>>>(Wfc, bfc, out);
}